// round 16
// baseline (speedup 1.0000x reference)
#include <cuda_runtime.h>
#include <math.h>

// ---------------- problem constants ----------------
#define Bv   2
#define Sv   2048
#define Ev   768
#define Hv   12
#define Dv   64
#define TBv  128
#define Mv   (Bv*Sv)      // 4096
#define BHv  (Bv*Hv)      // 24
#define SA   20           // smem row stride (floats) -> conflict-free frag loads

// ---------------- scratch (device globals) ------
__device__ float g_q  [BHv * Sv * Dv];   // [bh][s][d], tf32-rounded
__device__ float g_k  [BHv * Sv * Dv];   // [bh][s][d], tf32-rounded
__device__ float g_vt [BHv * Dv * Sv];   // [bh][d][s], TRANSPOSED, tf32-rounded
__device__ float g_ctx[BHv * Sv * Dv];   // [bh][s][d], tf32-rounded
__device__ float g_tb [BHv];

// ---------------- helpers --------------------------------------------------
__device__ __forceinline__ unsigned f2tf(float f) {
    unsigned u;
    asm("cvt.rna.tf32.f32 %0, %1;" : "=r"(u) : "f"(f));
    return u;
}

__device__ __forceinline__ void mma8(float c[4], const unsigned a[4], const unsigned b[2]) {
    asm volatile(
        "mma.sync.aligned.m16n8k8.row.col.f32.tf32.tf32.f32 "
        "{%0,%1,%2,%3},{%4,%5,%6,%7},{%8,%9},{%0,%1,%2,%3};"
        : "+f"(c[0]), "+f"(c[1]), "+f"(c[2]), "+f"(c[3])
        : "r"(a[0]), "r"(a[1]), "r"(a[2]), "r"(a[3]), "r"(b[0]), "r"(b[1]));
}

// ---------------- task-bias projection -------------------------------------
__global__ void tb_kernel(const float* __restrict__ task_bias,
                          const float* __restrict__ Wtb,
                          const float* __restrict__ btb) {
    int i = threadIdx.x;
    if (i < BHv) {
        int b = i / Hv, h = i % Hv;
        float s = btb[h];
        const float* tbp = task_bias + b * TBv;
        const float* wp  = Wtb + h * TBv;
        #pragma unroll 8
        for (int t = 0; t < TBv; t++) s += tbp[t] * wp[t];
        g_tb[i] = s;
    }
}

// ---------------- QKV projection: C = X @ W^T + bias (tf32 MMA) ------------
// 128x128 block, 8 warps (4x2), warp tile 32x64. Outputs tf32-rounded into
// head layout (q,k: [bh][s][d]; v: transposed [bh][d][s]).
__global__ __launch_bounds__(256)
void proj_tf32(const float* __restrict__ X, const float* __restrict__ W,
               const float* __restrict__ bias, int which) {
    __shared__ unsigned As[128 * SA];
    __shared__ unsigned Bs[128 * SA];
    const int t    = threadIdx.x;
    const int m0   = blockIdx.y * 128;
    const int n0   = blockIdx.x * 128;
    const int w    = t >> 5, lane = t & 31;
    const int g    = lane >> 2, tig = lane & 3;
    const int wm   = (w & 3) * 32, wn = (w >> 2) * 64;
    const int srow = t >> 2, scg = (t & 3) << 2;

    float acc[2][8][4] = {};

    for (int kt = 0; kt < Ev / 16; kt++) {
        const int k0 = kt * 16;
        #pragma unroll
        for (int r = 0; r < 2; r++) {
            int row = srow + r * 64;
            float4 xa = *(const float4*)(X + (size_t)(m0 + row) * Ev + k0 + scg);
            As[row * SA + scg + 0] = f2tf(xa.x); As[row * SA + scg + 1] = f2tf(xa.y);
            As[row * SA + scg + 2] = f2tf(xa.z); As[row * SA + scg + 3] = f2tf(xa.w);
            float4 wa = *(const float4*)(W + (size_t)(n0 + row) * Ev + k0 + scg);
            Bs[row * SA + scg + 0] = f2tf(wa.x); Bs[row * SA + scg + 1] = f2tf(wa.y);
            Bs[row * SA + scg + 2] = f2tf(wa.z); Bs[row * SA + scg + 3] = f2tf(wa.w);
        }
        __syncthreads();
        #pragma unroll
        for (int ks = 0; ks < 2; ks++) {
            const int kk = ks * 8;
            unsigned a[2][4], b[8][2];
            #pragma unroll
            for (int mt = 0; mt < 2; mt++) {
                int r = wm + mt * 16 + g;
                a[mt][0] = As[r * SA + kk + tig];
                a[mt][1] = As[(r + 8) * SA + kk + tig];
                a[mt][2] = As[r * SA + kk + tig + 4];
                a[mt][3] = As[(r + 8) * SA + kk + tig + 4];
            }
            #pragma unroll
            for (int nt = 0; nt < 8; nt++) {
                int c = wn + nt * 8 + g;
                b[nt][0] = Bs[c * SA + kk + tig];
                b[nt][1] = Bs[c * SA + kk + tig + 4];
            }
            #pragma unroll
            for (int mt = 0; mt < 2; mt++)
                #pragma unroll
                for (int nt = 0; nt < 8; nt++)
                    mma8(acc[mt][nt], a[mt], b[nt]);
        }
        __syncthreads();
    }

    float* Out = (which == 0) ? g_q : g_k;
    #pragma unroll
    for (int mt = 0; mt < 2; mt++)
        #pragma unroll
        for (int half = 0; half < 2; half++) {
            int m = m0 + wm + mt * 16 + g + half * 8;
            int b = m >> 11, s = m & (Sv - 1);
            #pragma unroll
            for (int nt = 0; nt < 8; nt++) {
                int col = n0 + wn + nt * 8 + 2 * tig;
                float v0 = acc[mt][nt][half * 2 + 0] + bias[col];
                float v1 = acc[mt][nt][half * 2 + 1] + bias[col + 1];
                int h = col >> 6, d = col & 63;
                if (which == 2) {
                    size_t base = ((size_t)(b * Hv + h) * Dv + d) * Sv + s;
                    g_vt[base]      = __uint_as_float(f2tf(v0));
                    g_vt[base + Sv] = __uint_as_float(f2tf(v1));
                } else {
                    *(float2*)&Out[((size_t)(b * Hv + h) * Sv + s) * Dv + d] =
                        make_float2(__uint_as_float(f2tf(v0)), __uint_as_float(f2tf(v1)));
                }
            }
        }
}

// ---------------- scores: attn = (Q K^T)*0.125 + tb (tf32 MMA) -------------
__global__ __launch_bounds__(256)
void scores_tf32(float* __restrict__ attn) {
    __shared__ unsigned As[128 * SA];
    __shared__ unsigned Bs[128 * SA];
    const int t    = threadIdx.x;
    const int bh   = blockIdx.z;
    const int m0   = blockIdx.y * 128;
    const int n0   = blockIdx.x * 128;
    const int w    = t >> 5, lane = t & 31;
    const int g    = lane >> 2, tig = lane & 3;
    const int wm   = (w & 3) * 32, wn = (w >> 2) * 64;
    const int srow = t >> 2, scg = (t & 3) << 2;

    const float* Q = g_q + (size_t)bh * Sv * Dv;
    const float* K = g_k + (size_t)bh * Sv * Dv;

    float acc[2][8][4] = {};

    for (int kt = 0; kt < Dv / 16; kt++) {
        const int k0 = kt * 16;
        #pragma unroll
        for (int r = 0; r < 2; r++) {
            int row = srow + r * 64;
            float4 qa = *(const float4*)(Q + (size_t)(m0 + row) * Dv + k0 + scg);
            As[row * SA + scg + 0] = __float_as_uint(qa.x);
            As[row * SA + scg + 1] = __float_as_uint(qa.y);
            As[row * SA + scg + 2] = __float_as_uint(qa.z);
            As[row * SA + scg + 3] = __float_as_uint(qa.w);
            float4 ka = *(const float4*)(K + (size_t)(n0 + row) * Dv + k0 + scg);
            Bs[row * SA + scg + 0] = __float_as_uint(ka.x);
            Bs[row * SA + scg + 1] = __float_as_uint(ka.y);
            Bs[row * SA + scg + 2] = __float_as_uint(ka.z);
            Bs[row * SA + scg + 3] = __float_as_uint(ka.w);
        }
        __syncthreads();
        #pragma unroll
        for (int ks = 0; ks < 2; ks++) {
            const int kk = ks * 8;
            unsigned a[2][4], b[8][2];
            #pragma unroll
            for (int mt = 0; mt < 2; mt++) {
                int r = wm + mt * 16 + g;
                a[mt][0] = As[r * SA + kk + tig];
                a[mt][1] = As[(r + 8) * SA + kk + tig];
                a[mt][2] = As[r * SA + kk + tig + 4];
                a[mt][3] = As[(r + 8) * SA + kk + tig + 4];
            }
            #pragma unroll
            for (int nt = 0; nt < 8; nt++) {
                int c = wn + nt * 8 + g;
                b[nt][0] = Bs[c * SA + kk + tig];
                b[nt][1] = Bs[c * SA + kk + tig + 4];
            }
            #pragma unroll
            for (int mt = 0; mt < 2; mt++)
                #pragma unroll
                for (int nt = 0; nt < 8; nt++)
                    mma8(acc[mt][nt], a[mt], b[nt]);
        }
        __syncthreads();
    }

    const float tbv = g_tb[bh];
    #pragma unroll
    for (int mt = 0; mt < 2; mt++)
        #pragma unroll
        for (int half = 0; half < 2; half++) {
            int m = m0 + wm + mt * 16 + g + half * 8;
            size_t rowbase = ((size_t)bh * Sv + m) * Sv;
            #pragma unroll
            for (int nt = 0; nt < 8; nt++) {
                int col = n0 + wn + nt * 8 + 2 * tig;
                float v0 = acc[mt][nt][half * 2 + 0] * 0.125f + tbv;
                float v1 = acc[mt][nt][half * 2 + 1] * 0.125f + tbv;
                *(float2*)&attn[rowbase + col] = make_float2(v0, v1);
            }
        }
}

// ---------------- row softmax (in place), with mask -------------------------
__global__ __launch_bounds__(256)
void softmax_kernel(float* __restrict__ attn, const int* __restrict__ mask) {
    const size_t r = blockIdx.x;
    float* row = attn + r * (size_t)Sv;
    const int b = (int)(r / (size_t)(Hv * Sv));
    const int* mrow = mask + b * Sv;
    const int t = threadIdx.x;

    float v[8];
    float mx = -INFINITY;
    #pragma unroll
    for (int i = 0; i < 8; i++) {
        int c = t + i * 256;
        float f = row[c];
        if (mrow[c] == 0) f = -INFINITY;
        v[i] = f;
        mx = fmaxf(mx, f);
    }
    __shared__ float red[8];
    #pragma unroll
    for (int o = 16; o > 0; o >>= 1) mx = fmaxf(mx, __shfl_xor_sync(0xffffffffu, mx, o));
    if ((t & 31) == 0) red[t >> 5] = mx;
    __syncthreads();
    float bm = red[0];
    #pragma unroll
    for (int wq = 1; wq < 8; wq++) bm = fmaxf(bm, red[wq]);
    __syncthreads();

    float sum = 0.f;
    #pragma unroll
    for (int i = 0; i < 8; i++) {
        float e = __expf(v[i] - bm);
        v[i] = e;
        sum += e;
    }
    #pragma unroll
    for (int o = 16; o > 0; o >>= 1) sum += __shfl_xor_sync(0xffffffffu, sum, o);
    if ((t & 31) == 0) red[t >> 5] = sum;
    __syncthreads();
    float tot = 0.f;
    #pragma unroll
    for (int wq = 0; wq < 8; wq++) tot += red[wq];
    float inv = 1.f / tot;
    #pragma unroll
    for (int i = 0; i < 8; i++) row[t + i * 256] = v[i] * inv;
}

// ---------------- ctx = attn @ V (tf32 MMA, V pre-transposed) ---------------
// 128x64 block, 8 warps (4x2), warp tile 32x32.
__global__ __launch_bounds__(256)
void av_tf32(const float* __restrict__ attn) {
    __shared__ unsigned As[128 * SA];
    __shared__ unsigned Bs[64 * SA];
    const int t    = threadIdx.x;
    const int bh   = blockIdx.z;
    const int m0   = blockIdx.y * 128;
    const int w    = t >> 5, lane = t & 31;
    const int g    = lane >> 2, tig = lane & 3;
    const int wm   = (w & 3) * 32, wn = (w >> 2) * 32;
    const int srow = t >> 2, scg = (t & 3) << 2;

    const float* A  = attn + (size_t)bh * Sv * Sv;
    const float* VT = g_vt + (size_t)bh * Dv * Sv;

    float acc[2][4][4] = {};

    for (int kt = 0; kt < Sv / 16; kt++) {
        const int k0 = kt * 16;
        #pragma unroll
        for (int r = 0; r < 2; r++) {
            int row = srow + r * 64;
            float4 aa = *(const float4*)(A + (size_t)(m0 + row) * Sv + k0 + scg);
            As[row * SA + scg + 0] = f2tf(aa.x); As[row * SA + scg + 1] = f2tf(aa.y);
            As[row * SA + scg + 2] = f2tf(aa.z); As[row * SA + scg + 3] = f2tf(aa.w);
        }
        {   // V^T tile: 64 rows (d) x 16 cols (s), k-contiguous, pre-rounded bits
            float4 va = *(const float4*)(VT + (size_t)srow * Sv + k0 + scg);
            Bs[srow * SA + scg + 0] = __float_as_uint(va.x);
            Bs[srow * SA + scg + 1] = __float_as_uint(va.y);
            Bs[srow * SA + scg + 2] = __float_as_uint(va.z);
            Bs[srow * SA + scg + 3] = __float_as_uint(va.w);
        }
        __syncthreads();
        #pragma unroll
        for (int ks = 0; ks < 2; ks++) {
            const int kk = ks * 8;
            unsigned a[2][4], b[4][2];
            #pragma unroll
            for (int mt = 0; mt < 2; mt++) {
                int r = wm + mt * 16 + g;
                a[mt][0] = As[r * SA + kk + tig];
                a[mt][1] = As[(r + 8) * SA + kk + tig];
                a[mt][2] = As[r * SA + kk + tig + 4];
                a[mt][3] = As[(r + 8) * SA + kk + tig + 4];
            }
            #pragma unroll
            for (int nt = 0; nt < 4; nt++) {
                int c = wn + nt * 8 + g;
                b[nt][0] = Bs[c * SA + kk + tig];
                b[nt][1] = Bs[c * SA + kk + tig + 4];
            }
            #pragma unroll
            for (int mt = 0; mt < 2; mt++)
                #pragma unroll
                for (int nt = 0; nt < 4; nt++)
                    mma8(acc[mt][nt], a[mt], b[nt]);
        }
        __syncthreads();
    }

    #pragma unroll
    for (int mt = 0; mt < 2; mt++)
        #pragma unroll
        for (int half = 0; half < 2; half++) {
            int m = m0 + wm + mt * 16 + g + half * 8;
            size_t rowbase = ((size_t)bh * Sv + m) * Dv;
            #pragma unroll
            for (int nt = 0; nt < 4; nt++) {
                int col = wn + nt * 8 + 2 * tig;
                float v0 = acc[mt][nt][half * 2 + 0];
                float v1 = acc[mt][nt][half * 2 + 1];
                *(float2*)&g_ctx[rowbase + col] =
                    make_float2(__uint_as_float(f2tf(v0)), __uint_as_float(f2tf(v1)));
            }
        }
}

// ---------------- out = ctx(gathered) @ Wo^T + bo (tf32 MMA) ----------------
__global__ __launch_bounds__(256)
void oproj_tf32(const float* __restrict__ Wo, const float* __restrict__ bo,
                float* __restrict__ out) {
    __shared__ unsigned As[128 * SA];
    __shared__ unsigned Bs[128 * SA];
    const int t    = threadIdx.x;
    const int m0   = blockIdx.y * 128;
    const int n0   = blockIdx.x * 128;
    const int w    = t >> 5, lane = t & 31;
    const int g    = lane >> 2, tig = lane & 3;
    const int wm   = (w & 3) * 32, wn = (w >> 2) * 64;
    const int srow = t >> 2, scg = (t & 3) << 2;

    float acc[2][8][4] = {};

    for (int kt = 0; kt < Ev / 16; kt++) {
        const int k0 = kt * 16;
        #pragma unroll
        for (int r = 0; r < 2; r++) {
            int row = srow + r * 64;
            int m = m0 + row;
            int b = m >> 11, s = m & (Sv - 1);
            int k = k0 + scg;
            int h = k >> 6, d = k & 63;
            float4 xa = *(const float4*)(g_ctx + ((size_t)(b * Hv + h) * Sv + s) * Dv + d);
            As[row * SA + scg + 0] = __float_as_uint(xa.x);
            As[row * SA + scg + 1] = __float_as_uint(xa.y);
            As[row * SA + scg + 2] = __float_as_uint(xa.z);
            As[row * SA + scg + 3] = __float_as_uint(xa.w);
            float4 wa = *(const float4*)(Wo + (size_t)(n0 + row) * Ev + k0 + scg);
            Bs[row * SA + scg + 0] = f2tf(wa.x); Bs[row * SA + scg + 1] = f2tf(wa.y);
            Bs[row * SA + scg + 2] = f2tf(wa.z); Bs[row * SA + scg + 3] = f2tf(wa.w);
        }
        __syncthreads();
        #pragma unroll
        for (int ks = 0; ks < 2; ks++) {
            const int kk = ks * 8;
            unsigned a[2][4], b[8][2];
            #pragma unroll
            for (int mt = 0; mt < 2; mt++) {
                int r = wm + mt * 16 + g;
                a[mt][0] = As[r * SA + kk + tig];
                a[mt][1] = As[(r + 8) * SA + kk + tig];
                a[mt][2] = As[r * SA + kk + tig + 4];
                a[mt][3] = As[(r + 8) * SA + kk + tig + 4];
            }
            #pragma unroll
            for (int nt = 0; nt < 8; nt++) {
                int c = wn + nt * 8 + g;
                b[nt][0] = Bs[c * SA + kk + tig];
                b[nt][1] = Bs[c * SA + kk + tig + 4];
            }
            #pragma unroll
            for (int mt = 0; mt < 2; mt++)
                #pragma unroll
                for (int nt = 0; nt < 8; nt++)
                    mma8(acc[mt][nt], a[mt], b[nt]);
        }
        __syncthreads();
    }

    #pragma unroll
    for (int mt = 0; mt < 2; mt++)
        #pragma unroll
        for (int half = 0; half < 2; half++) {
            int m = m0 + wm + mt * 16 + g + half * 8;
            #pragma unroll
            for (int nt = 0; nt < 8; nt++) {
                int col = n0 + wn + nt * 8 + 2 * tig;
                float v0 = acc[mt][nt][half * 2 + 0] + bo[col];
                float v1 = acc[mt][nt][half * 2 + 1] + bo[col + 1];
                *(float2*)&out[(size_t)m * Ev + col] = make_float2(v0, v1);
            }
        }
}

// ---------------- launch -----------------------------------------------------
extern "C" void kernel_launch(void* const* d_in, const int* in_sizes, int n_in,
                              void* d_out, int out_size) {
    const float* query     = (const float*)d_in[0];
    const float* key       = (const float*)d_in[1];
    const float* value     = (const float*)d_in[2];
    const float* task_bias = (const float*)d_in[3];
    const int*   mask      = (const int*)  d_in[4];
    const float* Wq  = (const float*)d_in[5];  const float* bq  = (const float*)d_in[6];
    const float* Wk  = (const float*)d_in[7];  const float* bk  = (const float*)d_in[8];
    const float* Wv  = (const float*)d_in[9];  const float* bv  = (const float*)d_in[10];
    const float* Wtb = (const float*)d_in[11]; const float* btb = (const float*)d_in[12];
    const float* Wo  = (const float*)d_in[13]; const float* bo  = (const float*)d_in[14];

    float* outp = (float*)d_out;
    float* attn = outp + (size_t)Bv * Sv * Ev;

    tb_kernel<<<1, 32>>>(task_bias, Wtb, btb);

    dim3 pg(Ev / 128, Mv / 128);                 // (6, 32)
    proj_tf32<<<pg, 256>>>(query, Wq, bq, 0);
    proj_tf32<<<pg, 256>>>(key,   Wk, bk, 1);
    proj_tf32<<<pg, 256>>>(value, Wv, bv, 2);

    dim3 sg(Sv / 128, Sv / 128, BHv);            // (16, 16, 24)
    scores_tf32<<<sg, 256>>>(attn);

    softmax_kernel<<<BHv * Sv, 256>>>(attn, mask);

    dim3 ag(1, Sv / 128, BHv);                   // (1, 16, 24)
    av_tf32<<<ag, 256>>>(attn);

    oproj_tf32<<<pg, 256>>>(Wo, bo, outp);
}

// round 17
// speedup vs baseline: 1.4512x; 1.4512x over previous
#include <cuda_runtime.h>
#include <math.h>

// ---------------- problem constants ----------------
#define Bv   2
#define Sv   2048
#define Ev   768
#define Hv   12
#define Dv   64
#define TBv  128
#define Mv   (Bv*Sv)      // 4096
#define BHv  (Bv*Hv)      // 24
#define SA   20           // smem row stride (floats): conflict-free + 16B-aligned rows

// ---------------- scratch (device globals) ------
__device__ float g_q  [BHv * Sv * Dv];   // [bh][s][d], tf32-rounded
__device__ float g_k  [BHv * Sv * Dv];   // [bh][s][d], tf32-rounded
__device__ float g_vt [BHv * Dv * Sv];   // [bh][d][s], transposed, tf32-rounded
__device__ float g_ctx[BHv * Sv * Dv];   // [bh][s][d], tf32-rounded
__device__ float g_tb [BHv];

// ---------------- helpers --------------------------------------------------
__device__ __forceinline__ unsigned f2tf(float f) {
    unsigned u;
    asm("cvt.rna.tf32.f32 %0, %1;" : "=r"(u) : "f"(f));
    return u;
}
__device__ __forceinline__ void mma8(float c[4], const unsigned a[4], const unsigned b[2]) {
    asm volatile(
        "mma.sync.aligned.m16n8k8.row.col.f32.tf32.tf32.f32 "
        "{%0,%1,%2,%3},{%4,%5,%6,%7},{%8,%9},{%0,%1,%2,%3};"
        : "+f"(c[0]), "+f"(c[1]), "+f"(c[2]), "+f"(c[3])
        : "r"(a[0]), "r"(a[1]), "r"(a[2]), "r"(a[3]), "r"(b[0]), "r"(b[1]));
}
__device__ __forceinline__ void cpa16(unsigned dst, const void* src) {
    asm volatile("cp.async.ca.shared.global [%0], [%1], 16;" :: "r"(dst), "l"(src));
}
__device__ __forceinline__ void cpcommit() {
    asm volatile("cp.async.commit_group;" ::: "memory");
}
template<int N> __device__ __forceinline__ void cpwait() {
    asm volatile("cp.async.wait_group %0;" :: "n"(N) : "memory");
}

// ---------------- task-bias projection -------------------------------------
__global__ void tb_kernel(const float* __restrict__ task_bias,
                          const float* __restrict__ Wtb,
                          const float* __restrict__ btb) {
    int i = threadIdx.x;
    if (i < BHv) {
        int b = i / Hv, h = i % Hv;
        float s = btb[h];
        const float* tbp = task_bias + b * TBv;
        const float* wp  = Wtb + h * TBv;
        #pragma unroll 8
        for (int t = 0; t < TBv; t++) s += tbp[t] * wp[t];
        g_tb[i] = s;
    }
}

// ---------------- fused QKV projection (pipelined tf32 MMA) ----------------
// blockIdx.z selects q/k/v. 128x128 tile, 8 warps (4x2), warp tile 32x64,
// 2-stage cp.async double buffer, cvt.rna after LDS.
__global__ __launch_bounds__(256)
void qkv_tf32(const float* __restrict__ Xq, const float* __restrict__ Xk,
              const float* __restrict__ Xv,
              const float* __restrict__ Wq, const float* __restrict__ Wk,
              const float* __restrict__ Wv,
              const float* __restrict__ bq, const float* __restrict__ bk,
              const float* __restrict__ bv) {
    __shared__ float As[2][128 * SA];
    __shared__ float Bs[2][128 * SA];
    const int which = blockIdx.z;
    const float* X    = (which == 0) ? Xq : (which == 1) ? Xk : Xv;
    const float* W    = (which == 0) ? Wq : (which == 1) ? Wk : Wv;
    const float* bias = (which == 0) ? bq : (which == 1) ? bk : bv;

    const int t    = threadIdx.x;
    const int m0   = blockIdx.y * 128;
    const int n0   = blockIdx.x * 128;
    const int w    = t >> 5, lane = t & 31;
    const int g    = lane >> 2, tig = lane & 3;
    const int wm   = (w & 3) * 32, wn = (w >> 2) * 64;
    const int srow = t >> 2, scg = (t & 3) << 2;
    const unsigned asb = (unsigned)__cvta_generic_to_shared(&As[0][0]);
    const unsigned bsb = (unsigned)__cvta_generic_to_shared(&Bs[0][0]);
    const int KT = Ev / 16;   // 48

    float acc[2][8][4] = {};

    auto issue = [&](int kt) {
        const int st = kt & 1;
        const unsigned ao = asb + st * (128 * SA * 4);
        const unsigned bo = bsb + st * (128 * SA * 4);
        const int k0 = kt * 16;
        #pragma unroll
        for (int r = 0; r < 2; r++) {
            int row = srow + r * 64;
            cpa16(ao + (row * SA + scg) * 4, X + (size_t)(m0 + row) * Ev + k0 + scg);
            cpa16(bo + (row * SA + scg) * 4, W + (size_t)(n0 + row) * Ev + k0 + scg);
        }
        cpcommit();
    };

    issue(0);
    for (int kt = 0; kt < KT; kt++) {
        if (kt + 1 < KT) { issue(kt + 1); cpwait<1>(); } else cpwait<0>();
        __syncthreads();
        const float* Af = &As[kt & 1][0];
        const float* Bf = &Bs[kt & 1][0];
        #pragma unroll
        for (int ks = 0; ks < 2; ks++) {
            const int kk = ks * 8;
            unsigned a[2][4], b[8][2];
            #pragma unroll
            for (int mt = 0; mt < 2; mt++) {
                int r = wm + mt * 16 + g;
                a[mt][0] = f2tf(Af[r * SA + kk + tig]);
                a[mt][1] = f2tf(Af[(r + 8) * SA + kk + tig]);
                a[mt][2] = f2tf(Af[r * SA + kk + tig + 4]);
                a[mt][3] = f2tf(Af[(r + 8) * SA + kk + tig + 4]);
            }
            #pragma unroll
            for (int nt = 0; nt < 8; nt++) {
                int c = wn + nt * 8 + g;
                b[nt][0] = f2tf(Bf[c * SA + kk + tig]);
                b[nt][1] = f2tf(Bf[c * SA + kk + tig + 4]);
            }
            #pragma unroll
            for (int mt = 0; mt < 2; mt++)
                #pragma unroll
                for (int nt = 0; nt < 8; nt++)
                    mma8(acc[mt][nt], a[mt], b[nt]);
        }
        __syncthreads();
    }

    float* Out = (which == 0) ? g_q : g_k;
    #pragma unroll
    for (int mt = 0; mt < 2; mt++)
        #pragma unroll
        for (int half = 0; half < 2; half++) {
            int m = m0 + wm + mt * 16 + g + half * 8;
            int b = m >> 11, s = m & (Sv - 1);
            #pragma unroll
            for (int nt = 0; nt < 8; nt++) {
                int col = n0 + wn + nt * 8 + 2 * tig;
                float v0 = acc[mt][nt][half * 2 + 0] + bias[col];
                float v1 = acc[mt][nt][half * 2 + 1] + bias[col + 1];
                int h = col >> 6, d = col & 63;
                if (which == 2) {
                    size_t base = ((size_t)(b * Hv + h) * Dv + d) * Sv + s;
                    g_vt[base]      = __uint_as_float(f2tf(v0));
                    g_vt[base + Sv] = __uint_as_float(f2tf(v1));
                } else {
                    *(float2*)&Out[((size_t)(b * Hv + h) * Sv + s) * Dv + d] =
                        make_float2(__uint_as_float(f2tf(v0)), __uint_as_float(f2tf(v1)));
                }
            }
        }
}

// ---------------- scores: attn = (Q K^T)*0.125 + tb (pipelined) -------------
__global__ __launch_bounds__(256)
void scores_tf32(float* __restrict__ attn) {
    __shared__ float As[2][128 * SA];
    __shared__ float Bs[2][128 * SA];
    const int t    = threadIdx.x;
    const int bh   = blockIdx.z;
    const int m0   = blockIdx.y * 128;
    const int n0   = blockIdx.x * 128;
    const int w    = t >> 5, lane = t & 31;
    const int g    = lane >> 2, tig = lane & 3;
    const int wm   = (w & 3) * 32, wn = (w >> 2) * 64;
    const int srow = t >> 2, scg = (t & 3) << 2;
    const unsigned asb = (unsigned)__cvta_generic_to_shared(&As[0][0]);
    const unsigned bsb = (unsigned)__cvta_generic_to_shared(&Bs[0][0]);

    const float* Q = g_q + (size_t)bh * Sv * Dv;
    const float* K = g_k + (size_t)bh * Sv * Dv;
    const int KT = Dv / 16;   // 4

    float acc[2][8][4] = {};

    auto issue = [&](int kt) {
        const int st = kt & 1;
        const unsigned ao = asb + st * (128 * SA * 4);
        const unsigned bo = bsb + st * (128 * SA * 4);
        const int k0 = kt * 16;
        #pragma unroll
        for (int r = 0; r < 2; r++) {
            int row = srow + r * 64;
            cpa16(ao + (row * SA + scg) * 4, Q + (size_t)(m0 + row) * Dv + k0 + scg);
            cpa16(bo + (row * SA + scg) * 4, K + (size_t)(n0 + row) * Dv + k0 + scg);
        }
        cpcommit();
    };

    issue(0);
    for (int kt = 0; kt < KT; kt++) {
        if (kt + 1 < KT) { issue(kt + 1); cpwait<1>(); } else cpwait<0>();
        __syncthreads();
        const float* Af = &As[kt & 1][0];
        const float* Bf = &Bs[kt & 1][0];
        #pragma unroll
        for (int ks = 0; ks < 2; ks++) {
            const int kk = ks * 8;
            unsigned a[2][4], b[8][2];
            #pragma unroll
            for (int mt = 0; mt < 2; mt++) {
                int r = wm + mt * 16 + g;
                a[mt][0] = __float_as_uint(Af[r * SA + kk + tig]);
                a[mt][1] = __float_as_uint(Af[(r + 8) * SA + kk + tig]);
                a[mt][2] = __float_as_uint(Af[r * SA + kk + tig + 4]);
                a[mt][3] = __float_as_uint(Af[(r + 8) * SA + kk + tig + 4]);
            }
            #pragma unroll
            for (int nt = 0; nt < 8; nt++) {
                int c = wn + nt * 8 + g;
                b[nt][0] = __float_as_uint(Bf[c * SA + kk + tig]);
                b[nt][1] = __float_as_uint(Bf[c * SA + kk + tig + 4]);
            }
            #pragma unroll
            for (int mt = 0; mt < 2; mt++)
                #pragma unroll
                for (int nt = 0; nt < 8; nt++)
                    mma8(acc[mt][nt], a[mt], b[nt]);
        }
        __syncthreads();
    }

    const float tbv = g_tb[bh];
    #pragma unroll
    for (int mt = 0; mt < 2; mt++)
        #pragma unroll
        for (int half = 0; half < 2; half++) {
            int m = m0 + wm + mt * 16 + g + half * 8;
            size_t rowbase = ((size_t)bh * Sv + m) * Sv;
            #pragma unroll
            for (int nt = 0; nt < 8; nt++) {
                int col = n0 + wn + nt * 8 + 2 * tig;
                float v0 = acc[mt][nt][half * 2 + 0] * 0.125f + tbv;
                float v1 = acc[mt][nt][half * 2 + 1] * 0.125f + tbv;
                *(float2*)&attn[rowbase + col] = make_float2(v0, v1);
            }
        }
}

// ---------------- row softmax (in place, vectorized), with mask -------------
__global__ __launch_bounds__(256)
void softmax_kernel(float* __restrict__ attn, const int* __restrict__ mask) {
    const size_t r = blockIdx.x;
    float4* row = (float4*)(attn + r * (size_t)Sv);
    const int b = (int)(r / (size_t)(Hv * Sv));
    const int4* m4 = (const int4*)(mask + b * Sv);
    const int t = threadIdx.x;

    float4 v[2];
    float mx = -INFINITY;
    #pragma unroll
    for (int i = 0; i < 2; i++) {
        int idx = t + i * 256;
        float4 f = row[idx];
        int4 mm  = m4[idx];
        f.x = (mm.x == 0) ? -INFINITY : f.x;
        f.y = (mm.y == 0) ? -INFINITY : f.y;
        f.z = (mm.z == 0) ? -INFINITY : f.z;
        f.w = (mm.w == 0) ? -INFINITY : f.w;
        v[i] = f;
        mx = fmaxf(mx, fmaxf(fmaxf(f.x, f.y), fmaxf(f.z, f.w)));
    }
    __shared__ float red[8];
    #pragma unroll
    for (int o = 16; o > 0; o >>= 1) mx = fmaxf(mx, __shfl_xor_sync(0xffffffffu, mx, o));
    if ((t & 31) == 0) red[t >> 5] = mx;
    __syncthreads();
    float bm = red[0];
    #pragma unroll
    for (int wq = 1; wq < 8; wq++) bm = fmaxf(bm, red[wq]);
    __syncthreads();

    float sum = 0.f;
    #pragma unroll
    for (int i = 0; i < 2; i++) {
        v[i].x = __expf(v[i].x - bm);
        v[i].y = __expf(v[i].y - bm);
        v[i].z = __expf(v[i].z - bm);
        v[i].w = __expf(v[i].w - bm);
        sum += (v[i].x + v[i].y) + (v[i].z + v[i].w);
    }
    #pragma unroll
    for (int o = 16; o > 0; o >>= 1) sum += __shfl_xor_sync(0xffffffffu, sum, o);
    if ((t & 31) == 0) red[t >> 5] = sum;
    __syncthreads();
    float tot = 0.f;
    #pragma unroll
    for (int wq = 0; wq < 8; wq++) tot += red[wq];
    float inv = 1.f / tot;
    #pragma unroll
    for (int i = 0; i < 2; i++) {
        v[i].x *= inv; v[i].y *= inv; v[i].z *= inv; v[i].w *= inv;
        row[t + i * 256] = v[i];
    }
}

// ---------------- ctx = attn @ V (pipelined, V pre-transposed) --------------
__global__ __launch_bounds__(256)
void av_tf32(const float* __restrict__ attn) {
    __shared__ float As[2][128 * SA];
    __shared__ float Bs[2][64 * SA];
    const int t    = threadIdx.x;
    const int bh   = blockIdx.z;
    const int m0   = blockIdx.y * 128;
    const int w    = t >> 5, lane = t & 31;
    const int g    = lane >> 2, tig = lane & 3;
    const int wm   = (w & 3) * 32, wn = (w >> 2) * 32;
    const int srow = t >> 2, scg = (t & 3) << 2;
    const unsigned asb = (unsigned)__cvta_generic_to_shared(&As[0][0]);
    const unsigned bsb = (unsigned)__cvta_generic_to_shared(&Bs[0][0]);

    const float* A  = attn + (size_t)bh * Sv * Sv;
    const float* VT = g_vt + (size_t)bh * Dv * Sv;
    const int KT = Sv / 16;   // 128

    float acc[2][4][4] = {};

    auto issue = [&](int kt) {
        const int st = kt & 1;
        const unsigned ao = asb + st * (128 * SA * 4);
        const unsigned bo = bsb + st * (64 * SA * 4);
        const int k0 = kt * 16;
        #pragma unroll
        for (int r = 0; r < 2; r++) {
            int row = srow + r * 64;
            cpa16(ao + (row * SA + scg) * 4, A + (size_t)(m0 + row) * Sv + k0 + scg);
        }
        cpa16(bo + (srow * SA + scg) * 4, VT + (size_t)srow * Sv + k0 + scg);
        cpcommit();
    };

    issue(0);
    for (int kt = 0; kt < KT; kt++) {
        if (kt + 1 < KT) { issue(kt + 1); cpwait<1>(); } else cpwait<0>();
        __syncthreads();
        const float* Af = &As[kt & 1][0];
        const float* Bf = &Bs[kt & 1][0];
        #pragma unroll
        for (int ks = 0; ks < 2; ks++) {
            const int kk = ks * 8;
            unsigned a[2][4], b[4][2];
            #pragma unroll
            for (int mt = 0; mt < 2; mt++) {
                int r = wm + mt * 16 + g;
                a[mt][0] = f2tf(Af[r * SA + kk + tig]);
                a[mt][1] = f2tf(Af[(r + 8) * SA + kk + tig]);
                a[mt][2] = f2tf(Af[r * SA + kk + tig + 4]);
                a[mt][3] = f2tf(Af[(r + 8) * SA + kk + tig + 4]);
            }
            #pragma unroll
            for (int nt = 0; nt < 4; nt++) {
                int c = wn + nt * 8 + g;
                b[nt][0] = __float_as_uint(Bf[c * SA + kk + tig]);
                b[nt][1] = __float_as_uint(Bf[c * SA + kk + tig + 4]);
            }
            #pragma unroll
            for (int mt = 0; mt < 2; mt++)
                #pragma unroll
                for (int nt = 0; nt < 4; nt++)
                    mma8(acc[mt][nt], a[mt], b[nt]);
        }
        __syncthreads();
    }

    #pragma unroll
    for (int mt = 0; mt < 2; mt++)
        #pragma unroll
        for (int half = 0; half < 2; half++) {
            int m = m0 + wm + mt * 16 + g + half * 8;
            size_t rowbase = ((size_t)bh * Sv + m) * Dv;
            #pragma unroll
            for (int nt = 0; nt < 4; nt++) {
                int col = wn + nt * 8 + 2 * tig;
                float v0 = acc[mt][nt][half * 2 + 0];
                float v1 = acc[mt][nt][half * 2 + 1];
                *(float2*)&g_ctx[rowbase + col] =
                    make_float2(__uint_as_float(f2tf(v0)), __uint_as_float(f2tf(v1)));
            }
        }
}

// ---------------- out = ctx(gathered) @ Wo^T + bo (pipelined) ---------------
__global__ __launch_bounds__(256)
void oproj_tf32(const float* __restrict__ Wo, const float* __restrict__ bo,
                float* __restrict__ out) {
    __shared__ float As[2][128 * SA];
    __shared__ float Bs[2][128 * SA];
    const int t    = threadIdx.x;
    const int m0   = blockIdx.y * 128;
    const int n0   = blockIdx.x * 128;
    const int w    = t >> 5, lane = t & 31;
    const int g    = lane >> 2, tig = lane & 3;
    const int wm   = (w & 3) * 32, wn = (w >> 2) * 64;
    const int srow = t >> 2, scg = (t & 3) << 2;
    const unsigned asb = (unsigned)__cvta_generic_to_shared(&As[0][0]);
    const unsigned bsb = (unsigned)__cvta_generic_to_shared(&Bs[0][0]);
    const int KT = Ev / 16;   // 48

    float acc[2][8][4] = {};

    auto issue = [&](int kt) {
        const int st = kt & 1;
        const unsigned ao = asb + st * (128 * SA * 4);
        const unsigned bo2 = bsb + st * (128 * SA * 4);
        const int k0 = kt * 16;
        #pragma unroll
        for (int r = 0; r < 2; r++) {
            int row = srow + r * 64;
            int m = m0 + row;
            int b = m >> 11, s = m & (Sv - 1);
            int k = k0 + scg;
            int h = k >> 6, d = k & 63;
            cpa16(ao + (row * SA + scg) * 4,
                  g_ctx + ((size_t)(b * Hv + h) * Sv + s) * Dv + d);
            cpa16(bo2 + (row * SA + scg) * 4, Wo + (size_t)(n0 + row) * Ev + k0 + scg);
        }
        cpcommit();
    };

    issue(0);
    for (int kt = 0; kt < KT; kt++) {
        if (kt + 1 < KT) { issue(kt + 1); cpwait<1>(); } else cpwait<0>();
        __syncthreads();
        const float* Af = &As[kt & 1][0];
        const float* Bf = &Bs[kt & 1][0];
        #pragma unroll
        for (int ks = 0; ks < 2; ks++) {
            const int kk = ks * 8;
            unsigned a[2][4], b[8][2];
            #pragma unroll
            for (int mt = 0; mt < 2; mt++) {
                int r = wm + mt * 16 + g;
                a[mt][0] = __float_as_uint(Af[r * SA + kk + tig]);
                a[mt][1] = __float_as_uint(Af[(r + 8) * SA + kk + tig]);
                a[mt][2] = __float_as_uint(Af[r * SA + kk + tig + 4]);
                a[mt][3] = __float_as_uint(Af[(r + 8) * SA + kk + tig + 4]);
            }
            #pragma unroll
            for (int nt = 0; nt < 8; nt++) {
                int c = wn + nt * 8 + g;
                b[nt][0] = f2tf(Bf[c * SA + kk + tig]);
                b[nt][1] = f2tf(Bf[c * SA + kk + tig + 4]);
            }
            #pragma unroll
            for (int mt = 0; mt < 2; mt++)
                #pragma unroll
                for (int nt = 0; nt < 8; nt++)
                    mma8(acc[mt][nt], a[mt], b[nt]);
        }
        __syncthreads();
    }

    #pragma unroll
    for (int mt = 0; mt < 2; mt++)
        #pragma unroll
        for (int half = 0; half < 2; half++) {
            int m = m0 + wm + mt * 16 + g + half * 8;
            #pragma unroll
            for (int nt = 0; nt < 8; nt++) {
                int col = n0 + wn + nt * 8 + 2 * tig;
                float v0 = acc[mt][nt][half * 2 + 0] + bo[col];
                float v1 = acc[mt][nt][half * 2 + 1] + bo[col + 1];
                *(float2*)&out[(size_t)m * Ev + col] = make_float2(v0, v1);
            }
        }
}

// ---------------- launch -----------------------------------------------------
extern "C" void kernel_launch(void* const* d_in, const int* in_sizes, int n_in,
                              void* d_out, int out_size) {
    const float* query     = (const float*)d_in[0];
    const float* key       = (const float*)d_in[1];
    const float* value     = (const float*)d_in[2];
    const float* task_bias = (const float*)d_in[3];
    const int*   mask      = (const int*)  d_in[4];
    const float* Wq  = (const float*)d_in[5];  const float* bq  = (const float*)d_in[6];
    const float* Wk  = (const float*)d_in[7];  const float* bk  = (const float*)d_in[8];
    const float* Wv  = (const float*)d_in[9];  const float* bv  = (const float*)d_in[10];
    const float* Wtb = (const float*)d_in[11]; const float* btb = (const float*)d_in[12];
    const float* Wo  = (const float*)d_in[13]; const float* bo  = (const float*)d_in[14];

    float* outp = (float*)d_out;
    float* attn = outp + (size_t)Bv * Sv * Ev;

    tb_kernel<<<1, 32>>>(task_bias, Wtb, btb);

    dim3 qg(Ev / 128, Mv / 128, 3);              // (6, 32, 3) = 576 blocks
    qkv_tf32<<<qg, 256>>>(query, key, value, Wq, Wk, Wv, bq, bk, bv);

    dim3 sg(Sv / 128, Sv / 128, BHv);            // (16, 16, 24)
    scores_tf32<<<sg, 256>>>(attn);

    softmax_kernel<<<BHv * Sv, 256>>>(attn, mask);

    dim3 ag(1, Sv / 128, BHv);                   // (1, 16, 24)
    av_tf32<<<ag, 256>>>(attn);

    dim3 pg(Ev / 128, Mv / 128);                 // (6, 32)
    oproj_tf32<<<pg, 256>>>(Wo, bo, outp);
}